// round 4
// baseline (speedup 1.0000x reference)
#include <cuda_runtime.h>
#include <cuda_bf16.h>
#include <math.h>
#include <stdint.h>

#define NROWS 16384
#define DDIM  256
#define KCB   8192

#define OFF_Q   16384
#define OFF_ST  (16384 + NROWS*DDIM)
#define OFF_SC  (16384 + 2*NROWS*DDIM)

#define SLOTS 64
#define EPS 4e-4f

#define CTA_M 128
#define CTA_N 128
#define NTILES (KCB / CTA_N)            // 64
#define TILE_BYTES (CTA_M * DDIM * 2)   // 65536

// dynamic smem layout for scan kernel
#define SM_A   0
#define SM_B0  65536
#define SM_B1  131072
#define SM_RB  196608
#define SM_TOTAL (196608 + 512)

__device__ __nv_bfloat16 d_latbf[NROWS * DDIM];
__device__ __nv_bfloat16 d_cbbf[KCB * DDIM];
__device__ float  d_hist[KCB];
__device__ int    d_bidx[NROWS];
__device__ int    d_cnt[NROWS];
__device__ int    d_cand[NROWS * SLOTS];
__device__ double d_sqsum;

// ---------------------------------------------------------------------------
// helpers
// ---------------------------------------------------------------------------
__device__ __forceinline__ uint32_t smem_u32(const void* p) {
    uint32_t a;
    asm("{ .reg .u64 t; cvta.to.shared.u64 t, %1; cvt.u32.u64 %0, t; }" : "=r"(a) : "l"(p));
    return a;
}
__device__ __forceinline__ void cp_async16(uint32_t dst, const void* src) {
    asm volatile("cp.async.cg.shared.global [%0], [%1], 16;" :: "r"(dst), "l"(src) : "memory");
}
#define CP_COMMIT() asm volatile("cp.async.commit_group;" ::: "memory")
#define CP_WAIT(n)  asm volatile("cp.async.wait_group %0;" :: "n"(n) : "memory")

// order-preserving float<->int map (no NaNs present)
__device__ __forceinline__ int   fmap(float f)  { int i = __float_as_int(f); return i < 0 ? i ^ 0x7FFFFFFF : i; }
__device__ __forceinline__ float funmap(int u)  { if (u < 0) u ^= 0x7FFFFFFF; return __int_as_float(u); }

#define LDSM_X4(r0, r1, r2, r3, addr) \
    asm volatile("ldmatrix.sync.aligned.m8n8.x4.shared.b16 {%0,%1,%2,%3}, [%4];" \
        : "=r"(r0), "=r"(r1), "=r"(r2), "=r"(r3) : "r"(addr))

#define MMA16816(d, a, b0, b1) \
    asm volatile("mma.sync.aligned.m16n8k16.row.col.f32.bf16.bf16.f32 " \
        "{%0,%1,%2,%3}, {%4,%5,%6,%7}, {%8,%9}, {%0,%1,%2,%3};" \
        : "+f"((d)[0]), "+f"((d)[1]), "+f"((d)[2]), "+f"((d)[3]) \
        : "r"((a)[0]), "r"((a)[1]), "r"((a)[2]), "r"((a)[3]), "r"(b0), "r"(b1))

// blocked-atom SW128 layout: 4 chunks (64 bf16 cols = 128B) x [128 rows x 128B]
// addr(row, bytecol) = chunk*16KB + row*128 + (s16 ^ (row&7))*16
__device__ __forceinline__ uint32_t tile_addr(uint32_t base, int row, int bytecol) {
    uint32_t chunk = (uint32_t)(bytecol >> 7);
    uint32_t s = (uint32_t)((bytecol >> 4) & 7) ^ (uint32_t)(row & 7);
    return base + chunk * 16384u + (uint32_t)row * 128u + s * 16u;
}

// stage a 128-row x 256-col bf16 tile (coalesced 16B chunks, 256 threads)
__device__ __forceinline__ void load_tile256(uint32_t dst, const __nv_bfloat16* g, int tid) {
#pragma unroll
    for (int i = 0; i < 16; i++) {
        int s = tid + i * 256;
        int row = s >> 5, ch = s & 31;
        uint32_t off = (uint32_t)(ch >> 3) * 16384u + (uint32_t)row * 128u
                     + (uint32_t)(((ch & 7) ^ (row & 7)) * 16);
        cp_async16(dst + off, (const char*)g + (size_t)s * 16);
    }
}

// ---------------------------------------------------------------------------
// Kernel 1: fp32 -> bf16 conversion + zero accumulators
// ---------------------------------------------------------------------------
#define LATG (NROWS * DDIM / 4)
#define CBG  (KCB * DDIM / 4)
__global__ void k_convert(const float* __restrict__ lat, const float* __restrict__ cb) {
    int g = blockIdx.x * 256 + threadIdx.x;
    if (g < LATG) {
        float4 v = ((const float4*)lat)[g];
        __nv_bfloat162 p0 = __floats2bfloat162_rn(v.x, v.y);
        __nv_bfloat162 p1 = __floats2bfloat162_rn(v.z, v.w);
        uint2 o = { *(unsigned*)&p0, *(unsigned*)&p1 };
        ((uint2*)d_latbf)[g] = o;
    } else if (g - LATG < CBG) {
        int h = g - LATG;
        float4 v = ((const float4*)cb)[h];
        __nv_bfloat162 p0 = __floats2bfloat162_rn(v.x, v.y);
        __nv_bfloat162 p1 = __floats2bfloat162_rn(v.z, v.w);
        uint2 o = { *(unsigned*)&p0, *(unsigned*)&p1 };
        ((uint2*)d_cbbf)[h] = o;
    }
    if (g < KCB)   d_hist[g] = 0.f;
    if (g < NROWS) d_cnt[g]  = 0;
    if (g == 0)    d_sqsum   = 0.0;
}

// ---------------------------------------------------------------------------
// Kernel 2: mma.sync scan — per-row running max dot + candidate collection
// 128x128 CTA tile, 8 warps (2m x 4n), warp tile 64x32, K=256
// ---------------------------------------------------------------------------
__global__ __launch_bounds__(256, 1) void k_scan_mma() {
    extern __shared__ __align__(1024) char smem[];
    uint32_t sb = smem_u32(smem);
    const int tid = threadIdx.x;
    const int lane = tid & 31, wid = tid >> 5;
    const int wm = wid & 1, wn = wid >> 1;
    const int rowblk = blockIdx.x * CTA_M;
    int* Rb = (int*)(smem + SM_RB);
    if (tid < CTA_M) Rb[tid] = fmap(-3.0e38f);

    // prologue: A persistent + B tile 0
    load_tile256(sb + SM_A, d_latbf + (size_t)rowblk * DDIM, tid); CP_COMMIT();
    load_tile256(sb + SM_B0, d_cbbf, tid); CP_COMMIT();

    const int quad = lane >> 2, qt = lane & 3;
    // ldmatrix lane addressing
    const int a_row = wm * 64 + (lane & 15);
    const int a_ch  = (lane >> 4) * 16;                 // extra byte offset
    const int b_row = ((lane >> 4) << 3) + (lane & 7);  // within 16-row pair
    const int b_ch  = ((lane >> 3) & 1) * 16;

    for (int t = 0; t < NTILES; t++) {
        const uint32_t bcur = (t & 1) ? (sb + SM_B1) : (sb + SM_B0);
        const uint32_t bnxt = (t & 1) ? (sb + SM_B0) : (sb + SM_B1);
        if (t + 1 < NTILES) {
            load_tile256(bnxt, d_cbbf + (size_t)(t + 1) * CTA_N * DDIM, tid);
            CP_COMMIT();
            CP_WAIT(1);          // tile t resident (its group committed last iter)
        } else {
            CP_WAIT(0);
        }
        __syncthreads();

        float acc[4][4][4];
#pragma unroll
        for (int mi = 0; mi < 4; mi++)
#pragma unroll
            for (int ni = 0; ni < 4; ni++)
#pragma unroll
                for (int e = 0; e < 4; e++) acc[mi][ni][e] = 0.f;

#pragma unroll
        for (int ks = 0; ks < 16; ks++) {
            const int k0b = ks * 32;   // 16 bf16 = 32 bytes per k-step
            uint32_t a[4][4];
#pragma unroll
            for (int mi = 0; mi < 4; mi++) {
                uint32_t ad = tile_addr(sb + SM_A, a_row + mi * 16, k0b + a_ch);
                LDSM_X4(a[mi][0], a[mi][1], a[mi][2], a[mi][3], ad);
            }
            uint32_t b[4][2];
#pragma unroll
            for (int np = 0; np < 2; np++) {
                uint32_t bd = tile_addr(bcur, wn * 32 + np * 16 + b_row, k0b + b_ch);
                uint32_t r0, r1, r2, r3;
                LDSM_X4(r0, r1, r2, r3, bd);
                b[np * 2][0] = r0;     b[np * 2][1] = r1;
                b[np * 2 + 1][0] = r2; b[np * 2 + 1][1] = r3;
            }
#pragma unroll
            for (int mi = 0; mi < 4; mi++)
#pragma unroll
                for (int ni = 0; ni < 4; ni++)
                    MMA16816(acc[mi][ni], a[mi], b[ni][0], b[ni][1]);
        }
        __syncthreads();   // all warps done reading bcur before next-iter overwrite

        // epilogue: per-row running max + candidate collection
        const int kb = t * CTA_N;
#pragma unroll
        for (int mi = 0; mi < 4; mi++)
#pragma unroll
            for (int h = 0; h < 2; h++) {
                float mx = -3.0e38f;
#pragma unroll
                for (int ni = 0; ni < 4; ni++) {
                    mx = fmaxf(mx, acc[mi][ni][h * 2 + 0]);
                    mx = fmaxf(mx, acc[mi][ni][h * 2 + 1]);
                }
                mx = fmaxf(mx, __shfl_xor_sync(0xffffffffu, mx, 1));
                mx = fmaxf(mx, __shfl_xor_sync(0xffffffffu, mx, 2));
                if (qt == 0) {
                    int r = wm * 64 + mi * 16 + quad + h * 8;
                    int mm = fmap(mx);
                    if (mm > Rb[r]) atomicMax(&Rb[r], mm);
                }
            }
        __syncthreads();
#pragma unroll
        for (int mi = 0; mi < 4; mi++)
#pragma unroll
            for (int h = 0; h < 2; h++) {
                const int r = wm * 64 + mi * 16 + quad + h * 8;
                const float thr = funmap(Rb[r]) - EPS;
                const int grow = rowblk + r;
#pragma unroll
                for (int ni = 0; ni < 4; ni++)
#pragma unroll
                    for (int e = 0; e < 2; e++) {
                        float v = acc[mi][ni][h * 2 + e];
                        if (v > thr) {
                            int pos = atomicAdd(&d_cnt[grow], 1);
                            if (pos < SLOTS)
                                d_cand[grow * SLOTS + pos] = kb + wn * 32 + ni * 8 + qt * 2 + e;
                        }
                    }
            }
    }
}

// ---------------------------------------------------------------------------
// Kernel 3: exact re-evaluation of candidates, replicate reference rounding:
// q = fl( fl(xn2 + cn2) - 2*dot_f ), argmin with lowest-index ties.
// ---------------------------------------------------------------------------
__global__ __launch_bounds__(256) void k_exact(const float* __restrict__ lat,
                                               const float* __restrict__ cb,
                                               float* __restrict__ out) {
    const int tid = threadIdx.x;
    const int lane = tid & 31, w = tid >> 5;
    const int row = blockIdx.x * 8 + w;

    float x[8];
    {
        const float4* xr = (const float4*)(lat + (size_t)row * DDIM);
        float4 a = xr[lane * 2], b = xr[lane * 2 + 1];
        x[0]=a.x; x[1]=a.y; x[2]=a.z; x[3]=a.w;
        x[4]=b.x; x[5]=b.y; x[6]=b.z; x[7]=b.w;
    }
    double xs = 0.0;
#pragma unroll
    for (int i = 0; i < 8; i++) xs += (double)x[i] * (double)x[i];
#pragma unroll
    for (int o = 16; o; o >>= 1) xs += __shfl_xor_sync(0xffffffffu, xs, o);
    float xn2 = (float)xs;

    int   n     = d_cnt[row];
    bool  fallb = (n > SLOTS);
    int   ncand = fallb ? KCB : n;

    float bestq = 3.4e38f;
    int   besti = 0;

    for (int c = 0; c < ncand; c++) {
        int idx = fallb ? c : d_cand[row * SLOTS + c];
        const float4* cr = (const float4*)(cb + (size_t)idx * DDIM);
        float4 a = cr[lane * 2], b = cr[lane * 2 + 1];
        float cv[8] = {a.x, a.y, a.z, a.w, b.x, b.y, b.z, b.w};

        float hi = 0.f, co = 0.f, cn = 0.f;
#pragma unroll
        for (int i = 0; i < 8; i++) {
            float p = __fmul_rn(x[i], cv[i]);
            float e = __fmaf_rn(x[i], cv[i], -p);
            float t = __fadd_rn(hi, p);
            float z = __fsub_rn(t, hi);
            float q2 = __fadd_rn(__fsub_rn(hi, __fsub_rn(t, z)), __fsub_rn(p, z));
            hi = t; co = __fadd_rn(co, __fadd_rn(q2, e));
            cn = __fmaf_rn(cv[i], cv[i], cn);
        }
#pragma unroll
        for (int o = 16; o; o >>= 1) {
            float h2 = __shfl_xor_sync(0xffffffffu, hi, o);
            float c2 = __shfl_xor_sync(0xffffffffu, co, o);
            cn += __shfl_xor_sync(0xffffffffu, cn, o);
            float t = __fadd_rn(hi, h2);
            float z = __fsub_rn(t, hi);
            float q2 = __fadd_rn(__fsub_rn(hi, __fsub_rn(t, z)), __fsub_rn(h2, z));
            hi = t; co = __fadd_rn(co, __fadd_rn(c2, q2));
        }
        if (lane == 0) {
            float df = __fadd_rn(hi, co);
            float t1 = __fadd_rn(xn2, cn);
            float q  = __fadd_rn(t1, -__fmul_rn(2.f, df));
            if (q < bestq || (q == bestq && idx < besti)) { bestq = q; besti = idx; }
        }
    }
    if (lane == 0) {
        d_bidx[row] = besti;
        out[row] = (float)besti;
    }
}

// ---------------------------------------------------------------------------
// Kernel 4: gather -> quantized + st_quantized, MSE partials, histogram
// ---------------------------------------------------------------------------
__global__ __launch_bounds__(256) void k_gather(const float* __restrict__ lat,
                                                const float* __restrict__ mask,
                                                const float* __restrict__ cb,
                                                float* __restrict__ out) {
    __shared__ float wsum[8];
    const int tid = threadIdx.x;
    const int lane = tid & 31, w = tid >> 5;
    const int row = blockIdx.x * 8 + w;

    int idx = d_bidx[row];
    const float4* x = (const float4*)(lat + (size_t)row * DDIM);
    const float4* c = (const float4*)(cb + (size_t)idx * DDIM);
    float4* q  = (float4*)(out + OFF_Q  + (size_t)row * DDIM);
    float4* st = (float4*)(out + OFF_ST + (size_t)row * DDIM);

    float s = 0.f;
#pragma unroll
    for (int i = lane; i < DDIM / 4; i += 32) {
        float4 cv = c[i], xv = x[i];
        q[i]  = cv;
        st[i] = cv;
        float d0 = xv.x - cv.x, d1 = xv.y - cv.y;
        float d2 = xv.z - cv.z, d3 = xv.w - cv.w;
        s += d0 * d0 + d1 * d1 + d2 * d2 + d3 * d3;
    }
#pragma unroll
    for (int o = 16; o; o >>= 1) s += __shfl_xor_sync(0xffffffffu, s, o);
    if (lane == 0) {
        wsum[w] = s;
        atomicAdd(&d_hist[idx], mask[row]);
    }
    __syncthreads();
    if (tid == 0) {
        double t = 0.0;
#pragma unroll
        for (int i = 0; i < 8; i++) t += (double)wsum[i];
        atomicAdd(&d_sqsum, t);
    }
}

// ---------------------------------------------------------------------------
// Kernel 5: finalize losses + perplexity
// ---------------------------------------------------------------------------
__global__ void k_final(const float* __restrict__ mask, float* __restrict__ out) {
    __shared__ float sh[256];
    const int tid = threadIdx.x;

    float m = 0.f;
    for (int i = tid; i < NROWS; i += 256) m += mask[i];
    sh[tid] = m; __syncthreads();
    for (int o = 128; o; o >>= 1) { if (tid < o) sh[tid] += sh[tid + o]; __syncthreads(); }
    float denom = fmaxf(sh[0], 1.0f);
    __syncthreads();

    float e = 0.f;
    for (int k2 = tid; k2 < KCB; k2 += 256) {
        float p = d_hist[k2] / denom;
        e += p * logf(p + 1e-8f);
    }
    sh[tid] = e; __syncthreads();
    for (int o = 128; o; o >>= 1) { if (tid < o) sh[tid] += sh[tid + o]; __syncthreads(); }

    if (tid == 0) {
        double mse = d_sqsum / (double)((size_t)NROWS * DDIM);
        out[OFF_SC + 0] = (float)(mse * 0.25);
        out[OFF_SC + 1] = (float)mse;
        out[OFF_SC + 2] = expf(-sh[0]);
    }
}

// ---------------------------------------------------------------------------
extern "C" void kernel_launch(void* const* d_in, const int* in_sizes, int n_in,
                              void* d_out, int out_size) {
    const float* lat  = (const float*)d_in[0];
    const float* mask = (const float*)d_in[1];
    const float* cb   = (const float*)d_in[2];
    float* out = (float*)d_out;

    cudaFuncSetAttribute(k_scan_mma, cudaFuncAttributeMaxDynamicSharedMemorySize, SM_TOTAL);

    k_convert <<<(LATG + CBG + 255) / 256, 256>>>(lat, cb);
    k_scan_mma<<<NROWS / CTA_M, 256, SM_TOTAL>>>();
    k_exact   <<<NROWS / 8, 256>>>(lat, cb, out);
    k_gather  <<<NROWS / 8, 256>>>(lat, mask, cb, out);
    k_final   <<<1, 256>>>(mask, out);
}

// round 5
// speedup vs baseline: 1.8197x; 1.8197x over previous
#include <cuda_runtime.h>
#include <math.h>
#include <stdint.h>

#define NROWS 16384
#define DDIM  256
#define KCB   8192

#define OFF_Q   16384
#define OFF_ST  (16384 + NROWS*DDIM)
#define OFF_SC  (16384 + 2*NROWS*DDIM)

#define SLOTS 64
#define EPS 5e-5f

#define TM   128                 // rows per CTA
#define TKT  64                  // codebook cols per k-tile
#define DC   64                  // d per stage
#define NSTAGE ((KCB / TKT) * (DDIM / DC))   // 512

// smem word layout
#define AW   (DDIM * 132)        // As[256][132]  = 33792 words
#define BW   (DC * 17)           // one Bs sub-array [64][17] = 1088 words
#define SMEM_WORDS (AW + 4 * BW + TM)        // + Rb[128]
#define SMEM_BYTES (SMEM_WORDS * 4)          // 153088

__device__ float  d_hist[KCB];
__device__ int    d_bidx[NROWS];
__device__ int    d_cnt[NROWS];
__device__ int    d_cand[NROWS * SLOTS];
__device__ double d_sqsum;

// ---------------------------------------------------------------------------
// helpers
// ---------------------------------------------------------------------------
__device__ __forceinline__ int   fmap(float f)  { int i = __float_as_int(f); return i < 0 ? i ^ 0x7FFFFFFF : i; }
__device__ __forceinline__ float funmap(int u)  { if (u < 0) u ^= 0x7FFFFFFF; return __int_as_float(u); }

__device__ __forceinline__ void fma2(unsigned long long& d, unsigned long long a,
                                     unsigned long long b) {
    asm("fma.rn.f32x2 %0, %1, %2, %0;" : "+l"(d) : "l"(a), "l"(b));
}
__device__ __forceinline__ unsigned long long pack_dup(float f) {
    unsigned long long o;
    unsigned u = __float_as_uint(f);
    asm("mov.b64 %0, {%1, %1};" : "=l"(o) : "r"(u));
    return o;
}
__device__ __forceinline__ void unpack2(unsigned long long v, float& lo, float& hi) {
    unsigned a, b;
    asm("mov.b64 {%0, %1}, %2;" : "=r"(a), "=r"(b) : "l"(v));
    lo = __uint_as_float(a); hi = __uint_as_float(b);
}

// ---------------------------------------------------------------------------
// Kernel 1: zero accumulators
// ---------------------------------------------------------------------------
__global__ void k_init() {
    int i = blockIdx.x * 256 + threadIdx.x;
    if (i < KCB)   d_hist[i] = 0.f;
    if (i < NROWS) d_cnt[i]  = 0;
    if (i == 0)    d_sqsum   = 0.0;
}

// ---------------------------------------------------------------------------
// Kernel 2: packed-f32x2 FFMA scan — per-row running max dot + candidates
// CTA: 128 rows x 64-col k-tiles, 256 threads (tx=col/4, ty=row/8)
// ---------------------------------------------------------------------------
__global__ __launch_bounds__(256, 1) void k_scan_f2(const float* __restrict__ lat,
                                                    const float* __restrict__ cb) {
    extern __shared__ __align__(16) float smf[];
    float* As = smf;                 // [d][row]  stride 132
    float* Bs = smf + AW;            // 4 sub-arrays [d][17]
    int*   Rb = (int*)(smf + AW + 4 * BW);

    const int tid = threadIdx.x;
    const int tx = tid & 15, ty = tid >> 4;
    const int rowblk = blockIdx.x * TM;

    if (tid < TM) Rb[tid] = fmap(-3.0e38f);

    // ---- persistent A: [128 rows][256 d] -> As[d][row] ----
#pragma unroll
    for (int i = 0; i < 32; i++) {
        int s2 = tid + i * 256;
        int row = s2 >> 6, dq = s2 & 63;
        float4 v = *(const float4*)(lat + (size_t)(rowblk + row) * DDIM + dq * 4);
        As[(dq * 4 + 0) * 132 + row] = v.x;
        As[(dq * 4 + 1) * 132 + row] = v.y;
        As[(dq * 4 + 2) * 132 + row] = v.z;
        As[(dq * 4 + 3) * 132 + row] = v.w;
    }

    // ---- B stage prefetch registers ----
    float4 pf[4];
    {   // stage 0: kt=0, c=0
#pragma unroll
        for (int i = 0; i < 4; i++) {
            int s2 = tid + i * 256;
            int col = s2 >> 4, dq = s2 & 15;
            pf[i] = *(const float4*)(cb + (size_t)col * DDIM + dq * 4);
        }
    }
    __syncthreads();
    // store stage 0 into Bs
#pragma unroll
    for (int i = 0; i < 4; i++) {
        int s2 = tid + i * 256;
        int col = s2 >> 4, dq = s2 & 15;
        float* dst = Bs + (col & 3) * BW + (col >> 2);
        dst[(4 * dq + 0) * 17] = pf[i].x;
        dst[(4 * dq + 1) * 17] = pf[i].y;
        dst[(4 * dq + 2) * 17] = pf[i].z;
        dst[(4 * dq + 3) * 17] = pf[i].w;
    }
    __syncthreads();

    unsigned long long acc[4][4];
#pragma unroll
    for (int p = 0; p < 4; p++)
#pragma unroll
        for (int j = 0; j < 4; j++) acc[p][j] = 0ull;

    for (int s = 0; s < NSTAGE; s++) {
        const int kt = s >> 2, c = s & 3;

        // prefetch next stage's B into registers (latency hidden by compute)
        if (s + 1 < NSTAGE) {
            const int nkt = (s + 1) >> 2, nc = (s + 1) & 3;
            const float* gB = cb + (size_t)nkt * TKT * DDIM + nc * DC;
#pragma unroll
            for (int i = 0; i < 4; i++) {
                int s2 = tid + i * 256;
                int col = s2 >> 4, dq = s2 & 15;
                pf[i] = *(const float4*)(gB + (size_t)col * DDIM + dq * 4);
            }
        }

        // ---- compute this stage: 64 d-steps ----
        const int dbase = c * DC;
#pragma unroll 4
        for (int dd = 0; dd < DC; dd++) {
            const float* ap = As + (size_t)(dbase + dd) * 132 + 8 * ty;
            ulonglong2 a01 = *(const ulonglong2*)ap;
            ulonglong2 a23 = *(const ulonglong2*)(ap + 4);
            unsigned long long ar0 = a01.x, ar1 = a01.y, ar2 = a23.x, ar3 = a23.y;
            unsigned long long bb[4];
#pragma unroll
            for (int j = 0; j < 4; j++)
                bb[j] = pack_dup(Bs[j * BW + dd * 17 + tx]);
#pragma unroll
            for (int j = 0; j < 4; j++) {
                fma2(acc[0][j], ar0, bb[j]);
                fma2(acc[1][j], ar1, bb[j]);
                fma2(acc[2][j], ar2, bb[j]);
                fma2(acc[3][j], ar3, bb[j]);
            }
        }
        __syncthreads();                 // everyone done reading Bs(stage s)

        if (s + 1 < NSTAGE) {
#pragma unroll
            for (int i = 0; i < 4; i++) {
                int s2 = tid + i * 256;
                int col = s2 >> 4, dq = s2 & 15;
                float* dst = Bs + (col & 3) * BW + (col >> 2);
                dst[(4 * dq + 0) * 17] = pf[i].x;
                dst[(4 * dq + 1) * 17] = pf[i].y;
                dst[(4 * dq + 2) * 17] = pf[i].z;
                dst[(4 * dq + 3) * 17] = pf[i].w;
            }
            __syncthreads();
        }

        // ---- epilogue at end of each k-tile ----
        if (c == 3) {
            float vals[8][4];
#pragma unroll
            for (int p = 0; p < 4; p++)
#pragma unroll
                for (int j = 0; j < 4; j++) {
                    unpack2(acc[p][j], vals[2 * p][j], vals[2 * p + 1][j]);
                    acc[p][j] = 0ull;
                }
#pragma unroll
            for (int rr = 0; rr < 8; rr++) {
                float mx = fmaxf(fmaxf(vals[rr][0], vals[rr][1]),
                                 fmaxf(vals[rr][2], vals[rr][3]));
                mx = fmaxf(mx, __shfl_xor_sync(0xffffffffu, mx, 1));
                mx = fmaxf(mx, __shfl_xor_sync(0xffffffffu, mx, 2));
                mx = fmaxf(mx, __shfl_xor_sync(0xffffffffu, mx, 4));
                mx = fmaxf(mx, __shfl_xor_sync(0xffffffffu, mx, 8));
                if (tx == 0) {
                    int mm = fmap(mx);
                    if (mm > Rb[8 * ty + rr]) atomicMax(&Rb[8 * ty + rr], mm);
                }
            }
            __syncthreads();
#pragma unroll
            for (int rr = 0; rr < 8; rr++) {
                const float thr = funmap(Rb[8 * ty + rr]) - EPS;
                const int grow = rowblk + 8 * ty + rr;
#pragma unroll
                for (int j = 0; j < 4; j++) {
                    if (vals[rr][j] > thr) {
                        int pos = atomicAdd(&d_cnt[grow], 1);
                        if (pos < SLOTS)
                            d_cand[grow * SLOTS + pos] = kt * TKT + 4 * tx + j;
                    }
                }
            }
        }
    }
}

// ---------------------------------------------------------------------------
// Kernel 3: exact re-evaluation of candidates, replicate reference rounding:
// q = fl( fl(xn2 + cn2) - 2*dot_f ), argmin with lowest-index ties.
// ---------------------------------------------------------------------------
__global__ __launch_bounds__(256) void k_exact(const float* __restrict__ lat,
                                               const float* __restrict__ cb,
                                               float* __restrict__ out) {
    const int tid = threadIdx.x;
    const int lane = tid & 31, w = tid >> 5;
    const int row = blockIdx.x * 8 + w;

    float x[8];
    {
        const float4* xr = (const float4*)(lat + (size_t)row * DDIM);
        float4 a = xr[lane * 2], b = xr[lane * 2 + 1];
        x[0]=a.x; x[1]=a.y; x[2]=a.z; x[3]=a.w;
        x[4]=b.x; x[5]=b.y; x[6]=b.z; x[7]=b.w;
    }
    double xs = 0.0;
#pragma unroll
    for (int i = 0; i < 8; i++) xs += (double)x[i] * (double)x[i];
#pragma unroll
    for (int o = 16; o; o >>= 1) xs += __shfl_xor_sync(0xffffffffu, xs, o);
    float xn2 = (float)xs;

    int   n     = d_cnt[row];
    bool  fallb = (n > SLOTS);
    int   ncand = fallb ? KCB : n;

    float bestq = 3.4e38f;
    int   besti = 0;

    for (int c = 0; c < ncand; c++) {
        int idx = fallb ? c : d_cand[row * SLOTS + c];
        const float4* cr = (const float4*)(cb + (size_t)idx * DDIM);
        float4 a = cr[lane * 2], b = cr[lane * 2 + 1];
        float cv[8] = {a.x, a.y, a.z, a.w, b.x, b.y, b.z, b.w};

        float hi = 0.f, co = 0.f, cn = 0.f;
#pragma unroll
        for (int i = 0; i < 8; i++) {
            float p = __fmul_rn(x[i], cv[i]);
            float e = __fmaf_rn(x[i], cv[i], -p);
            float t = __fadd_rn(hi, p);
            float z = __fsub_rn(t, hi);
            float q2 = __fadd_rn(__fsub_rn(hi, __fsub_rn(t, z)), __fsub_rn(p, z));
            hi = t; co = __fadd_rn(co, __fadd_rn(q2, e));
            cn = __fmaf_rn(cv[i], cv[i], cn);
        }
#pragma unroll
        for (int o = 16; o; o >>= 1) {
            float h2 = __shfl_xor_sync(0xffffffffu, hi, o);
            float c2 = __shfl_xor_sync(0xffffffffu, co, o);
            cn += __shfl_xor_sync(0xffffffffu, cn, o);
            float t = __fadd_rn(hi, h2);
            float z = __fsub_rn(t, hi);
            float q2 = __fadd_rn(__fsub_rn(hi, __fsub_rn(t, z)), __fsub_rn(h2, z));
            hi = t; co = __fadd_rn(co, __fadd_rn(c2, q2));
        }
        if (lane == 0) {
            float df = __fadd_rn(hi, co);
            float t1 = __fadd_rn(xn2, cn);
            float q  = __fadd_rn(t1, -__fmul_rn(2.f, df));
            if (q < bestq || (q == bestq && idx < besti)) { bestq = q; besti = idx; }
        }
    }
    if (lane == 0) {
        d_bidx[row] = besti;
        out[row] = (float)besti;
    }
}

// ---------------------------------------------------------------------------
// Kernel 4: gather -> quantized + st_quantized, MSE partials, histogram
// ---------------------------------------------------------------------------
__global__ __launch_bounds__(256) void k_gather(const float* __restrict__ lat,
                                                const float* __restrict__ mask,
                                                const float* __restrict__ cb,
                                                float* __restrict__ out) {
    __shared__ float wsum[8];
    const int tid = threadIdx.x;
    const int lane = tid & 31, w = tid >> 5;
    const int row = blockIdx.x * 8 + w;

    int idx = d_bidx[row];
    const float4* x = (const float4*)(lat + (size_t)row * DDIM);
    const float4* c = (const float4*)(cb + (size_t)idx * DDIM);
    float4* q  = (float4*)(out + OFF_Q  + (size_t)row * DDIM);
    float4* st = (float4*)(out + OFF_ST + (size_t)row * DDIM);

    float s = 0.f;
#pragma unroll
    for (int i = lane; i < DDIM / 4; i += 32) {
        float4 cv = c[i], xv = x[i];
        q[i]  = cv;
        st[i] = cv;
        float d0 = xv.x - cv.x, d1 = xv.y - cv.y;
        float d2 = xv.z - cv.z, d3 = xv.w - cv.w;
        s += d0 * d0 + d1 * d1 + d2 * d2 + d3 * d3;
    }
#pragma unroll
    for (int o = 16; o; o >>= 1) s += __shfl_xor_sync(0xffffffffu, s, o);
    if (lane == 0) {
        wsum[w] = s;
        atomicAdd(&d_hist[idx], mask[row]);
    }
    __syncthreads();
    if (tid == 0) {
        double t = 0.0;
#pragma unroll
        for (int i = 0; i < 8; i++) t += (double)wsum[i];
        atomicAdd(&d_sqsum, t);
    }
}

// ---------------------------------------------------------------------------
// Kernel 5: finalize losses + perplexity
// ---------------------------------------------------------------------------
__global__ void k_final(const float* __restrict__ mask, float* __restrict__ out) {
    __shared__ float sh[256];
    const int tid = threadIdx.x;

    float m = 0.f;
    for (int i = tid; i < NROWS; i += 256) m += mask[i];
    sh[tid] = m; __syncthreads();
    for (int o = 128; o; o >>= 1) { if (tid < o) sh[tid] += sh[tid + o]; __syncthreads(); }
    float denom = fmaxf(sh[0], 1.0f);
    __syncthreads();

    float e = 0.f;
    for (int k2 = tid; k2 < KCB; k2 += 256) {
        float p = d_hist[k2] / denom;
        e += p * logf(p + 1e-8f);
    }
    sh[tid] = e; __syncthreads();
    for (int o = 128; o; o >>= 1) { if (tid < o) sh[tid] += sh[tid + o]; __syncthreads(); }

    if (tid == 0) {
        double mse = d_sqsum / (double)((size_t)NROWS * DDIM);
        out[OFF_SC + 0] = (float)(mse * 0.25);
        out[OFF_SC + 1] = (float)mse;
        out[OFF_SC + 2] = expf(-sh[0]);
    }
}

// ---------------------------------------------------------------------------
extern "C" void kernel_launch(void* const* d_in, const int* in_sizes, int n_in,
                              void* d_out, int out_size) {
    const float* lat  = (const float*)d_in[0];
    const float* mask = (const float*)d_in[1];
    const float* cb   = (const float*)d_in[2];
    float* out = (float*)d_out;

    cudaFuncSetAttribute(k_scan_f2, cudaFuncAttributeMaxDynamicSharedMemorySize, SMEM_BYTES);

    k_init   <<<NROWS / 256, 256>>>();
    k_scan_f2<<<NROWS / TM, 256, SMEM_BYTES>>>(lat, cb);
    k_exact  <<<NROWS / 8, 256>>>(lat, cb, out);
    k_gather <<<NROWS / 8, 256>>>(lat, mask, cb, out);
    k_final  <<<1, 256>>>(mask, out);
}

// round 6
// speedup vs baseline: 1.9147x; 1.0522x over previous
#include <cuda_runtime.h>
#include <math.h>
#include <stdint.h>

#define NROWS 16384
#define DDIM  256
#define KCB   8192

#define OFF_Q   16384
#define OFF_ST  (16384 + NROWS*DDIM)
#define OFF_SC  (16384 + 2*NROWS*DDIM)

#define SLOTS 64
#define EPS 5e-5f

#define TM   128                  // rows per rowblk
#define TKT  64                   // codebook cols per k-tile
#define DC   64                   // d per stage
#define KSLICE 1024               // codes per work unit
#define NRB   (NROWS / TM)        // 128 rowblks
#define NSL   (KCB / KSLICE)      // 8 slices
#define NUNITS (NRB * NSL)        // 1024
#define USTAGES ((KSLICE / TKT) * (DDIM / DC))   // 64 stages per unit
#define GRID_SCAN 148

// smem word layout
#define AW    (DDIM * 132)        // As[256][132] = 33792 words
#define BW    (DC * 17)           // one Bs sub-array [64][17] = 1088 words
#define BBUF  (4 * BW)            // 4 sub-arrays = 4352 words per buffer
#define SMEM_WORDS (AW + 2 * BBUF + TM)
#define SMEM_BYTES (SMEM_WORDS * 4)   // 170,496 B

__device__ float  d_hist[KCB];
__device__ int    d_bidx[NROWS];
__device__ int    d_cnt[NROWS];
__device__ int    d_cand[NROWS * SLOTS];
__device__ double d_sqsum;
__device__ int    d_wq;

// ---------------------------------------------------------------------------
// helpers
// ---------------------------------------------------------------------------
__device__ __forceinline__ int   fmap(float f)  { int i = __float_as_int(f); return i < 0 ? i ^ 0x7FFFFFFF : i; }
__device__ __forceinline__ float funmap(int u)  { if (u < 0) u ^= 0x7FFFFFFF; return __int_as_float(u); }

__device__ __forceinline__ void fma2(unsigned long long& d, unsigned long long a,
                                     unsigned long long b) {
    asm("fma.rn.f32x2 %0, %1, %2, %0;" : "+l"(d) : "l"(a), "l"(b));
}
__device__ __forceinline__ unsigned long long pack_dup(float f) {
    unsigned long long o;
    unsigned u = __float_as_uint(f);
    asm("mov.b64 %0, {%1, %1};" : "=l"(o) : "r"(u));
    return o;
}
__device__ __forceinline__ void unpack2(unsigned long long v, float& lo, float& hi) {
    unsigned a, b;
    asm("mov.b64 {%0, %1}, %2;" : "=r"(a), "=r"(b) : "l"(v));
    lo = __uint_as_float(a); hi = __uint_as_float(b);
}

// ---------------------------------------------------------------------------
// Kernel 1: zero accumulators + work-queue counter
// ---------------------------------------------------------------------------
__global__ void k_init() {
    int i = blockIdx.x * 256 + threadIdx.x;
    if (i < KCB)   d_hist[i] = 0.f;
    if (i < NROWS) d_cnt[i]  = 0;
    if (i == 0)  { d_sqsum   = 0.0; d_wq = 0; }
}

// ---------------------------------------------------------------------------
// Kernel 2: persistent work-queue packed-f32x2 scan
// unit = (rowblk of 128 rows) x (slice of 1024 codes); 256 threads
// ---------------------------------------------------------------------------
__global__ __launch_bounds__(256, 1) void k_scan_wq(const float* __restrict__ lat,
                                                    const float* __restrict__ cb) {
    extern __shared__ __align__(16) float smf[];
    float* As = smf;                       // [d][row] stride 132
    float* Bs = smf + AW;                  // 2 buffers x 4 sub-arrays [64][17]
    int*   Rb = (int*)(smf + AW + 2 * BBUF);

    const int tid = threadIdx.x;
    const int tx = tid & 15, ty = tid >> 4;
    __shared__ int s_unit;

    int cur_rb = -1;

    for (;;) {
        if (tid == 0) s_unit = atomicAdd(&d_wq, 1);
        __syncthreads();
        const int u = s_unit;
        if (u >= NUNITS) break;
        const int rbi = u >> 3;          // u / NSL
        const int ksl = u & 7;           // u % NSL
        const int rowblk = rbi * TM;

        if (rbi != cur_rb) {
            // reset running max + load A tile (transposed [d][row])
            if (tid < TM) Rb[tid] = fmap(-3.0e38f);
#pragma unroll
            for (int i = 0; i < 32; i++) {
                int s2 = tid + i * 256;
                int row = s2 >> 6, dq = s2 & 63;
                float4 v = *(const float4*)(lat + (size_t)(rowblk + row) * DDIM + dq * 4);
                As[(dq * 4 + 0) * 132 + row] = v.x;
                As[(dq * 4 + 1) * 132 + row] = v.y;
                As[(dq * 4 + 2) * 132 + row] = v.z;
                As[(dq * 4 + 3) * 132 + row] = v.w;
            }
            cur_rb = rbi;
            __syncthreads();
        }

        const float* cbS = cb + (size_t)ksl * KSLICE * DDIM;

        // prologue: stage 0 B -> Bs buffer 0
        float4 pf[4];
#pragma unroll
        for (int i = 0; i < 4; i++) {
            int s2 = tid + i * 256;
            int col = s2 >> 4, dq = s2 & 15;
            pf[i] = *(const float4*)(cbS + (size_t)col * DDIM + dq * 4);
        }
#pragma unroll
        for (int i = 0; i < 4; i++) {
            int s2 = tid + i * 256;
            int col = s2 >> 4, dq = s2 & 15;
            float* dst = Bs + (col & 3) * BW + (col >> 2);
            dst[(4 * dq + 0) * 17] = pf[i].x;
            dst[(4 * dq + 1) * 17] = pf[i].y;
            dst[(4 * dq + 2) * 17] = pf[i].z;
            dst[(4 * dq + 3) * 17] = pf[i].w;
        }
        __syncthreads();

        unsigned long long acc[4][4];
#pragma unroll
        for (int p = 0; p < 4; p++)
#pragma unroll
            for (int j = 0; j < 4; j++) acc[p][j] = 0ull;

        for (int s = 0; s < USTAGES; s++) {
            const int kt = s >> 2, c = s & 3;
            const uint32_t buf = (uint32_t)(s & 1);
            float* Bcur = Bs + buf * BBUF;
            float* Bnxt = Bs + (buf ^ 1) * BBUF;

            // prefetch next stage's B into registers
            if (s + 1 < USTAGES) {
                const int ns = s + 1, nkt = ns >> 2, nc = ns & 3;
                const float* gB = cbS + (size_t)nkt * TKT * DDIM + nc * DC;
#pragma unroll
                for (int i = 0; i < 4; i++) {
                    int s2 = tid + i * 256;
                    int col = s2 >> 4, dq = s2 & 15;
                    pf[i] = *(const float4*)(gB + (size_t)col * DDIM + dq * 4);
                }
            }

            // compute this stage: 64 d-steps
            const int dbase = c * DC;
#pragma unroll 4
            for (int dd = 0; dd < DC; dd++) {
                const float* ap = As + (size_t)(dbase + dd) * 132 + 8 * ty;
                ulonglong2 a01 = *(const ulonglong2*)ap;
                ulonglong2 a23 = *(const ulonglong2*)(ap + 4);
                unsigned long long ar0 = a01.x, ar1 = a01.y, ar2 = a23.x, ar3 = a23.y;
                unsigned long long bb[4];
#pragma unroll
                for (int j = 0; j < 4; j++)
                    bb[j] = pack_dup(Bcur[j * BW + dd * 17 + tx]);
#pragma unroll
                for (int j = 0; j < 4; j++) {
                    fma2(acc[0][j], ar0, bb[j]);
                    fma2(acc[1][j], ar1, bb[j]);
                    fma2(acc[2][j], ar2, bb[j]);
                    fma2(acc[3][j], ar3, bb[j]);
                }
            }

            // store prefetched B into the other buffer
            if (s + 1 < USTAGES) {
#pragma unroll
                for (int i = 0; i < 4; i++) {
                    int s2 = tid + i * 256;
                    int col = s2 >> 4, dq = s2 & 15;
                    float* dst = Bnxt + (col & 3) * BW + (col >> 2);
                    dst[(4 * dq + 0) * 17] = pf[i].x;
                    dst[(4 * dq + 1) * 17] = pf[i].y;
                    dst[(4 * dq + 2) * 17] = pf[i].z;
                    dst[(4 * dq + 3) * 17] = pf[i].w;
                }
            }
            __syncthreads();

            // epilogue at end of each 64-col k-tile
            if (c == 3) {
                float vals[8][4];
#pragma unroll
                for (int p = 0; p < 4; p++)
#pragma unroll
                    for (int j = 0; j < 4; j++) {
                        unpack2(acc[p][j], vals[2 * p][j], vals[2 * p + 1][j]);
                        acc[p][j] = 0ull;
                    }
#pragma unroll
                for (int rr = 0; rr < 8; rr++) {
                    float mx = fmaxf(fmaxf(vals[rr][0], vals[rr][1]),
                                     fmaxf(vals[rr][2], vals[rr][3]));
                    mx = fmaxf(mx, __shfl_xor_sync(0xffffffffu, mx, 1));
                    mx = fmaxf(mx, __shfl_xor_sync(0xffffffffu, mx, 2));
                    mx = fmaxf(mx, __shfl_xor_sync(0xffffffffu, mx, 4));
                    mx = fmaxf(mx, __shfl_xor_sync(0xffffffffu, mx, 8));
                    if (tx == 0) {
                        int mm = fmap(mx);
                        if (mm > Rb[8 * ty + rr]) atomicMax(&Rb[8 * ty + rr], mm);
                    }
                }
                __syncthreads();
                const int kbase = ksl * KSLICE + kt * TKT;
#pragma unroll
                for (int rr = 0; rr < 8; rr++) {
                    const float thr = funmap(Rb[8 * ty + rr]) - EPS;
                    const int grow = rowblk + 8 * ty + rr;
#pragma unroll
                    for (int j = 0; j < 4; j++) {
                        if (vals[rr][j] > thr) {
                            int pos = atomicAdd(&d_cnt[grow], 1);
                            if (pos < SLOTS)
                                d_cand[grow * SLOTS + pos] = kbase + 4 * tx + j;
                        }
                    }
                }
            }
        }
    }
}

// ---------------------------------------------------------------------------
// Kernel 3: exact re-evaluation of candidates, replicate reference rounding:
// q = fl( fl(xn2 + cn2) - 2*dot_f ), argmin with lowest-index ties.
// ---------------------------------------------------------------------------
__global__ __launch_bounds__(256) void k_exact(const float* __restrict__ lat,
                                               const float* __restrict__ cb,
                                               float* __restrict__ out) {
    const int tid = threadIdx.x;
    const int lane = tid & 31, w = tid >> 5;
    const int row = blockIdx.x * 8 + w;

    float x[8];
    {
        const float4* xr = (const float4*)(lat + (size_t)row * DDIM);
        float4 a = xr[lane * 2], b = xr[lane * 2 + 1];
        x[0]=a.x; x[1]=a.y; x[2]=a.z; x[3]=a.w;
        x[4]=b.x; x[5]=b.y; x[6]=b.z; x[7]=b.w;
    }
    double xs = 0.0;
#pragma unroll
    for (int i = 0; i < 8; i++) xs += (double)x[i] * (double)x[i];
#pragma unroll
    for (int o = 16; o; o >>= 1) xs += __shfl_xor_sync(0xffffffffu, xs, o);
    float xn2 = (float)xs;

    int   n     = d_cnt[row];
    bool  fallb = (n > SLOTS);
    int   ncand = fallb ? KCB : n;

    float bestq = 3.4e38f;
    int   besti = 0;

    for (int c = 0; c < ncand; c++) {
        int idx = fallb ? c : d_cand[row * SLOTS + c];
        const float4* cr = (const float4*)(cb + (size_t)idx * DDIM);
        float4 a = cr[lane * 2], b = cr[lane * 2 + 1];
        float cv[8] = {a.x, a.y, a.z, a.w, b.x, b.y, b.z, b.w};

        float hi = 0.f, co = 0.f, cn = 0.f;
#pragma unroll
        for (int i = 0; i < 8; i++) {
            float p = __fmul_rn(x[i], cv[i]);
            float e = __fmaf_rn(x[i], cv[i], -p);
            float t = __fadd_rn(hi, p);
            float z = __fsub_rn(t, hi);
            float q2 = __fadd_rn(__fsub_rn(hi, __fsub_rn(t, z)), __fsub_rn(p, z));
            hi = t; co = __fadd_rn(co, __fadd_rn(q2, e));
            cn = __fmaf_rn(cv[i], cv[i], cn);
        }
#pragma unroll
        for (int o = 16; o; o >>= 1) {
            float h2 = __shfl_xor_sync(0xffffffffu, hi, o);
            float c2 = __shfl_xor_sync(0xffffffffu, co, o);
            cn += __shfl_xor_sync(0xffffffffu, cn, o);
            float t = __fadd_rn(hi, h2);
            float z = __fsub_rn(t, hi);
            float q2 = __fadd_rn(__fsub_rn(hi, __fsub_rn(t, z)), __fsub_rn(h2, z));
            hi = t; co = __fadd_rn(co, __fadd_rn(c2, q2));
        }
        if (lane == 0) {
            float df = __fadd_rn(hi, co);
            float t1 = __fadd_rn(xn2, cn);
            float q  = __fadd_rn(t1, -__fmul_rn(2.f, df));
            if (q < bestq || (q == bestq && idx < besti)) { bestq = q; besti = idx; }
        }
    }
    if (lane == 0) {
        d_bidx[row] = besti;
        out[row] = (float)besti;
    }
}

// ---------------------------------------------------------------------------
// Kernel 4: gather -> quantized + st_quantized, MSE partials, histogram
// ---------------------------------------------------------------------------
__global__ __launch_bounds__(256) void k_gather(const float* __restrict__ lat,
                                                const float* __restrict__ mask,
                                                const float* __restrict__ cb,
                                                float* __restrict__ out) {
    __shared__ float wsum[8];
    const int tid = threadIdx.x;
    const int lane = tid & 31, w = tid >> 5;
    const int row = blockIdx.x * 8 + w;

    int idx = d_bidx[row];
    const float4* x = (const float4*)(lat + (size_t)row * DDIM);
    const float4* c = (const float4*)(cb + (size_t)idx * DDIM);
    float4* q  = (float4*)(out + OFF_Q  + (size_t)row * DDIM);
    float4* st = (float4*)(out + OFF_ST + (size_t)row * DDIM);

    float s = 0.f;
#pragma unroll
    for (int i = lane; i < DDIM / 4; i += 32) {
        float4 cv = c[i], xv = x[i];
        q[i]  = cv;
        st[i] = cv;
        float d0 = xv.x - cv.x, d1 = xv.y - cv.y;
        float d2 = xv.z - cv.z, d3 = xv.w - cv.w;
        s += d0 * d0 + d1 * d1 + d2 * d2 + d3 * d3;
    }
#pragma unroll
    for (int o = 16; o; o >>= 1) s += __shfl_xor_sync(0xffffffffu, s, o);
    if (lane == 0) {
        wsum[w] = s;
        atomicAdd(&d_hist[idx], mask[row]);
    }
    __syncthreads();
    if (tid == 0) {
        double t = 0.0;
#pragma unroll
        for (int i = 0; i < 8; i++) t += (double)wsum[i];
        atomicAdd(&d_sqsum, t);
    }
}

// ---------------------------------------------------------------------------
// Kernel 5: finalize losses + perplexity
// ---------------------------------------------------------------------------
__global__ void k_final(const float* __restrict__ mask, float* __restrict__ out) {
    __shared__ float sh[256];
    const int tid = threadIdx.x;

    float m = 0.f;
    for (int i = tid; i < NROWS; i += 256) m += mask[i];
    sh[tid] = m; __syncthreads();
    for (int o = 128; o; o >>= 1) { if (tid < o) sh[tid] += sh[tid + o]; __syncthreads(); }
    float denom = fmaxf(sh[0], 1.0f);
    __syncthreads();

    float e = 0.f;
    for (int k2 = tid; k2 < KCB; k2 += 256) {
        float p = d_hist[k2] / denom;
        e += p * logf(p + 1e-8f);
    }
    sh[tid] = e; __syncthreads();
    for (int o = 128; o; o >>= 1) { if (tid < o) sh[tid] += sh[tid + o]; __syncthreads(); }

    if (tid == 0) {
        double mse = d_sqsum / (double)((size_t)NROWS * DDIM);
        out[OFF_SC + 0] = (float)(mse * 0.25);
        out[OFF_SC + 1] = (float)mse;
        out[OFF_SC + 2] = expf(-sh[0]);
    }
}

// ---------------------------------------------------------------------------
extern "C" void kernel_launch(void* const* d_in, const int* in_sizes, int n_in,
                              void* d_out, int out_size) {
    const float* lat  = (const float*)d_in[0];
    const float* mask = (const float*)d_in[1];
    const float* cb   = (const float*)d_in[2];
    float* out = (float*)d_out;

    cudaFuncSetAttribute(k_scan_wq, cudaFuncAttributeMaxDynamicSharedMemorySize, SMEM_BYTES);

    k_init   <<<NROWS / 256, 256>>>();
    k_scan_wq<<<GRID_SCAN, 256, SMEM_BYTES>>>(lat, cb);
    k_exact  <<<NROWS / 8, 256>>>(lat, cb, out);
    k_gather <<<NROWS / 8, 256>>>(lat, mask, cb, out);
    k_final  <<<1, 256>>>(mask, out);
}